// round 1
// baseline (speedup 1.0000x reference)
#include <cuda_runtime.h>
#include <cuda_bf16.h>
#include <math_constants.h>

// Problem constants (DistanceNetwork_17514876634042)
#define BB     8
#define SS     4096
#define QQ     4096
#define DD     64
#define BSHOT  2048
#define NTOP   5
#define OUTC   (NTOP + (SS - BSHOT))   // 2053

// Scratch: cos values for support columns [0, BSHOT) -> fed to top-5 pass.
// 8*4096*2048 floats = 268 MB. Static __device__ globals are allowed.
__device__ float g_cos[(size_t)BB * QQ * BSHOT];
// Per-(b,s) inverse magnitudes.
__device__ float g_mag[BB * SS];

// ---------------------------------------------------------------------------
// Kernel 1: support magnitudes  mag[b,s] = rsqrt(max(sum_d s^2, 1e-10))
// ---------------------------------------------------------------------------
__global__ void mag_kernel(const float* __restrict__ supp) {
    int i = blockIdx.x * blockDim.x + threadIdx.x;
    if (i >= BB * SS) return;
    const float* p = supp + (size_t)i * DD;
    float s = 0.f;
#pragma unroll
    for (int k = 0; k < DD; k += 4) {
        float4 v = *(const float4*)(p + k);
        s += v.x * v.x + v.y * v.y + v.z * v.z + v.w * v.w;
    }
    g_mag[i] = rsqrtf(fmaxf(s, 1e-10f));
}

// ---------------------------------------------------------------------------
// Kernel 2: fused cosine GEMM.
//   64x64 output tile per CTA (256 threads), K=64 fully resident.
//   thread (ty,tx) with ty=tid/16, tx=tid%16 owns rows {i*16+ty}, cols {j*16+tx}
//   -> conflict-free smem reads (row stride 65) and coalesced global stores.
//   cols >= BSHOT stream straight to d_out; cols < BSHOT go to g_cos scratch.
// ---------------------------------------------------------------------------
__global__ __launch_bounds__(256) void gemm_kernel(const float* __restrict__ supp,
                                                   const float* __restrict__ query,
                                                   float* __restrict__ out) {
    __shared__ float Qs[64 * 65];
    __shared__ float Sh[64 * 65];
    __shared__ float Ms[64];

    const int b  = blockIdx.z;
    const int q0 = blockIdx.x * 64;
    const int s0 = blockIdx.y * 64;
    const int tid = threadIdx.x;

    const float* qb = query + (size_t)b * QQ * DD;
    const float* sb = supp  + (size_t)b * SS * DD;

    // Cooperative tile load: 16 rows x 64 cols per pass, 4 passes. float4 global reads.
    const int lr = tid / 16;          // 0..15
    const int lc = (tid % 16) * 4;    // 0,4,...,60
#pragma unroll
    for (int r = lr; r < 64; r += 16) {
        float4 v = *(const float4*)(qb + (size_t)(q0 + r) * DD + lc);
        Qs[r * 65 + lc + 0] = v.x; Qs[r * 65 + lc + 1] = v.y;
        Qs[r * 65 + lc + 2] = v.z; Qs[r * 65 + lc + 3] = v.w;
        float4 w = *(const float4*)(sb + (size_t)(s0 + r) * DD + lc);
        Sh[r * 65 + lc + 0] = w.x; Sh[r * 65 + lc + 1] = w.y;
        Sh[r * 65 + lc + 2] = w.z; Sh[r * 65 + lc + 3] = w.w;
    }
    if (tid < 64) Ms[tid] = g_mag[b * SS + s0 + tid];
    __syncthreads();

    const int ty = tid / 16;
    const int tx = tid % 16;

    float acc[4][4];
#pragma unroll
    for (int i = 0; i < 4; i++)
#pragma unroll
        for (int j = 0; j < 4; j++) acc[i][j] = 0.f;

#pragma unroll 16
    for (int k = 0; k < 64; ++k) {
        float a[4], c[4];
#pragma unroll
        for (int i = 0; i < 4; i++) a[i] = Qs[(i * 16 + ty) * 65 + k];
#pragma unroll
        for (int j = 0; j < 4; j++) c[j] = Sh[(j * 16 + tx) * 65 + k];
#pragma unroll
        for (int i = 0; i < 4; i++)
#pragma unroll
            for (int j = 0; j < 4; j++)
                acc[i][j] = fmaf(a[i], c[j], acc[i][j]);
    }

    float m[4];
#pragma unroll
    for (int j = 0; j < 4; j++) m[j] = Ms[j * 16 + tx];

    const bool tail = (s0 >= BSHOT);   // uniform per CTA (BSHOT % 64 == 0)
#pragma unroll
    for (int i = 0; i < 4; i++) {
        const int q = q0 + i * 16 + ty;
        if (tail) {
            float* orow = out + ((size_t)b * QQ + q) * OUTC + NTOP + (s0 - BSHOT);
#pragma unroll
            for (int j = 0; j < 4; j++)
                orow[j * 16 + tx] = acc[i][j] * m[j];
        } else {
            float* crow = g_cos + ((size_t)b * QQ + q) * BSHOT + s0;
#pragma unroll
            for (int j = 0; j < 4; j++)
                crow[j * 16 + tx] = acc[i][j] * m[j];
        }
    }
}

// ---------------------------------------------------------------------------
// Kernel 3: top-5 (sorted descending) over g_cos rows. One warp per (b,q).
// ---------------------------------------------------------------------------
__global__ __launch_bounds__(256) void top5_kernel(float* __restrict__ out) {
    const int warp_global = (blockIdx.x * blockDim.x + threadIdx.x) >> 5;
    const int lane = threadIdx.x & 31;
    if (warp_global >= BB * QQ) return;

    const float* row = g_cos + (size_t)warp_global * BSHOT;

    float a0 = -CUDART_INF_F, a1 = -CUDART_INF_F, a2 = -CUDART_INF_F,
          a3 = -CUDART_INF_F, a4 = -CUDART_INF_F;

#pragma unroll 4
    for (int i = lane; i < BSHOT; i += 32) {
        float v = row[i];
        if (v > a4) {
            a4 = v;
            if (a4 > a3) { float t = a3; a3 = a4; a4 = t;
                if (a3 > a2) { t = a2; a2 = a3; a3 = t;
                    if (a2 > a1) { t = a1; a1 = a2; a2 = t;
                        if (a1 > a0) { t = a0; a0 = a1; a1 = t; } } } }
        }
    }

    // 5 rounds of warp argmax-pop; each round emits the next largest value.
    float* orow = out + (size_t)warp_global * OUTC;
    float cur = a0;
#pragma unroll
    for (int r = 0; r < NTOP; r++) {
        float mx = cur;
#pragma unroll
        for (int off = 16; off; off >>= 1)
            mx = fmaxf(mx, __shfl_xor_sync(0xffffffffu, mx, off));
        unsigned ball = __ballot_sync(0xffffffffu, cur == mx);
        int winner = __ffs(ball) - 1;
        if (lane == winner) {
            cur = a1; a1 = a2; a2 = a3; a3 = a4; a4 = -CUDART_INF_F;
        }
        if (lane == 0) orow[r] = mx;
    }
}

// ---------------------------------------------------------------------------
extern "C" void kernel_launch(void* const* d_in, const int* in_sizes, int n_in,
                              void* d_out, int out_size) {
    const float* supp  = (const float*)d_in[0];
    const float* query = (const float*)d_in[1];
    float* out = (float*)d_out;

    mag_kernel<<<(BB * SS + 255) / 256, 256>>>(supp);

    dim3 grid(QQ / 64, SS / 64, BB);
    gemm_kernel<<<grid, 256>>>(supp, query, out);

    top5_kernel<<<(BB * QQ) / 8, 256>>>(out);
}

// round 2
// speedup vs baseline: 1.6741x; 1.6741x over previous
#include <cuda_runtime.h>
#include <cuda_bf16.h>
#include <math_constants.h>

// Problem constants (DistanceNetwork_17514876634042)
#define BB     8
#define SS     4096
#define QQ     4096
#define DD     64
#define BSHOT  2048
#define NTOP   5
#define OUTC   (NTOP + (SS - BSHOT))   // 2053

#define TM     128          // q rows per CTA
#define TN     128          // s cols per tile
#define NTILES (SS / TN)    // 32
#define TOPTILES (BSHOT / TN) // 16 tiles feed top-5
#define STRIDE 68           // smem row stride (floats): 64 + 4 pad -> conflict-free frags
#define TILE_FLOATS (TM * STRIDE)   // 8704

__device__ float g_mag[BB * SS];

// ---------------------------------------------------------------------------
__global__ void mag_kernel(const float* __restrict__ supp) {
    int i = blockIdx.x * blockDim.x + threadIdx.x;
    if (i >= BB * SS) return;
    const float* p = supp + (size_t)i * DD;
    float s = 0.f;
#pragma unroll
    for (int k = 0; k < DD; k += 4) {
        float4 v = *(const float4*)(p + k);
        s += v.x * v.x + v.y * v.y + v.z * v.z + v.w * v.w;
    }
    g_mag[i] = rsqrtf(fmaxf(s, 1e-10f));
}

// ---------------------------------------------------------------------------
__device__ __forceinline__ unsigned f2tf32(float f) {
    unsigned u;
    asm("cvt.rna.tf32.f32 %0, %1;" : "=r"(u) : "f"(f));
    return u;
}

__device__ __forceinline__ void mma_tf32(float& c0, float& c1, float& c2, float& c3,
                                         unsigned a0, unsigned a1, unsigned a2, unsigned a3,
                                         unsigned b0, unsigned b1) {
    asm volatile(
        "mma.sync.aligned.m16n8k8.row.col.f32.tf32.tf32.f32 "
        "{%0,%1,%2,%3}, {%4,%5,%6,%7}, {%8,%9}, {%0,%1,%2,%3};"
        : "+f"(c0), "+f"(c1), "+f"(c2), "+f"(c3)
        : "r"(a0), "r"(a1), "r"(a2), "r"(a3), "r"(b0), "r"(b1));
}

__device__ __forceinline__ void ins5(float* t, float v) {
    if (v > t[4]) {
        t[4] = v;
        if (t[4] > t[3]) { float x = t[3]; t[3] = t[4]; t[4] = x;
            if (t[3] > t[2]) { x = t[2]; t[2] = t[3]; t[3] = x;
                if (t[2] > t[1]) { x = t[1]; t[1] = t[2]; t[2] = x;
                    if (t[1] > t[0]) { x = t[0]; t[0] = t[1]; t[1] = x; } } } }
    }
}

// ---------------------------------------------------------------------------
// Fused: tf32 MMA cosine GEMM + direct tail store + register-resident top-5.
// Grid: (QQ/TM, BB). 256 threads = 8 warps in 4(M) x 2(N).
// ---------------------------------------------------------------------------
extern __shared__ unsigned smem_raw[];

__global__ __launch_bounds__(256, 1)
void fused_kernel(const float* __restrict__ supp,
                  const float* __restrict__ query,
                  float* __restrict__ out) {
    unsigned* Qs = smem_raw;                 // TILE_FLOATS
    unsigned* Ss = smem_raw + TILE_FLOATS;   // 2 * TILE_FLOATS (double buffer)
    float* red = (float*)(smem_raw + TILE_FLOATS);  // aliases Ss buf0 at the end

    const int b  = blockIdx.y;
    const int q0 = blockIdx.x * TM;
    const int tid = threadIdx.x;
    const int wid = tid >> 5;
    const int lane = tid & 31;
    const int wm = wid >> 1;        // 0..3
    const int wn = wid & 1;         // 0..1
    const int qd = lane >> 2;       // 0..7
    const int kq = lane & 3;        // 0..3

    const float* qb = query + (size_t)b * QQ * DD;
    const float* sb = supp  + (size_t)b * SS * DD;

    // --- load Q tile once (with RNA tf32 rounding) ---
    {
        const int row = tid >> 1;
        const int half = (tid & 1) * 32;
        const float* p = qb + (size_t)(q0 + row) * DD + half;
        unsigned* d = Qs + row * STRIDE + half;
#pragma unroll
        for (int i = 0; i < 8; i++) {
            float4 v = *(const float4*)(p + i * 4);
            d[i * 4 + 0] = f2tf32(v.x);
            d[i * 4 + 1] = f2tf32(v.y);
            d[i * 4 + 2] = f2tf32(v.z);
            d[i * 4 + 3] = f2tf32(v.w);
        }
    }

    // --- S tile prefetch machinery (register double-buffer + mag folding) ---
    const int srow = tid >> 1;
    const int shalf = (tid & 1) * 32;
    float4 pf[8];
    float pmag;

    // prefetch tile 0
    {
        const float* p = sb + (size_t)srow * DD + shalf;
#pragma unroll
        for (int i = 0; i < 8; i++) pf[i] = *(const float4*)(p + i * 4);
        pmag = g_mag[b * SS + srow];
    }
    // store tile 0 into buf 0
    {
        unsigned* d = Ss + srow * STRIDE + shalf;
#pragma unroll
        for (int i = 0; i < 8; i++) {
            d[i * 4 + 0] = f2tf32(pf[i].x * pmag);
            d[i * 4 + 1] = f2tf32(pf[i].y * pmag);
            d[i * 4 + 2] = f2tf32(pf[i].z * pmag);
            d[i * 4 + 3] = f2tf32(pf[i].w * pmag);
        }
    }
    __syncthreads();

    float tops[4][5];
#pragma unroll
    for (int r = 0; r < 4; r++)
#pragma unroll
        for (int i = 0; i < 5; i++) tops[r][i] = -CUDART_INF_F;

    for (int st = 0; st < NTILES; ++st) {
        // prefetch next tile into registers
        if (st + 1 < NTILES) {
            const float* p = sb + (size_t)((st + 1) * TN + srow) * DD + shalf;
#pragma unroll
            for (int i = 0; i < 8; i++) pf[i] = *(const float4*)(p + i * 4);
            pmag = g_mag[b * SS + (st + 1) * TN + srow];
        }

        const unsigned* Bs = Ss + (st & 1) * TILE_FLOATS;

        float c[2][8][4];
#pragma unroll
        for (int mi = 0; mi < 2; mi++)
#pragma unroll
            for (int ni = 0; ni < 8; ni++)
#pragma unroll
                for (int j = 0; j < 4; j++) c[mi][ni][j] = 0.f;

#pragma unroll
        for (int k0 = 0; k0 < DD; k0 += 8) {
            unsigned a[2][4];
#pragma unroll
            for (int mi = 0; mi < 2; mi++) {
                const unsigned* ab = Qs + (wm * 32 + mi * 16 + qd) * STRIDE + k0 + kq;
                a[mi][0] = ab[0];
                a[mi][1] = ab[8 * STRIDE];
                a[mi][2] = ab[4];
                a[mi][3] = ab[8 * STRIDE + 4];
            }
#pragma unroll
            for (int ni = 0; ni < 8; ni++) {
                const unsigned* bb = Bs + (wn * 64 + ni * 8 + qd) * STRIDE + k0 + kq;
                unsigned b0 = bb[0];
                unsigned b1 = bb[4];
                mma_tf32(c[0][ni][0], c[0][ni][1], c[0][ni][2], c[0][ni][3],
                         a[0][0], a[0][1], a[0][2], a[0][3], b0, b1);
                mma_tf32(c[1][ni][0], c[1][ni][1], c[1][ni][2], c[1][ni][3],
                         a[1][0], a[1][1], a[1][2], a[1][3], b0, b1);
            }
        }

        // epilogue for this tile
        if (st >= TOPTILES) {
            // tail columns -> direct store to out
            const int s0 = st * TN;
            float* ob = out + (size_t)(b * QQ + q0) * OUTC + NTOP + (s0 - BSHOT);
#pragma unroll
            for (int mi = 0; mi < 2; mi++) {
                const int r0 = wm * 32 + mi * 16 + qd;
#pragma unroll
                for (int ni = 0; ni < 8; ni++) {
                    const int cb = wn * 64 + ni * 8 + kq * 2;
                    ob[(size_t)r0 * OUTC + cb]           = c[mi][ni][0];
                    ob[(size_t)r0 * OUTC + cb + 1]       = c[mi][ni][1];
                    ob[(size_t)(r0 + 8) * OUTC + cb]     = c[mi][ni][2];
                    ob[(size_t)(r0 + 8) * OUTC + cb + 1] = c[mi][ni][3];
                }
            }
        } else {
            // top-5 update: slot = mi*2 + (cj>=2), rows r_base + slot*8
#pragma unroll
            for (int mi = 0; mi < 2; mi++)
#pragma unroll
                for (int ni = 0; ni < 8; ni++) {
                    ins5(tops[mi * 2 + 0], c[mi][ni][0]);
                    ins5(tops[mi * 2 + 0], c[mi][ni][1]);
                    ins5(tops[mi * 2 + 1], c[mi][ni][2]);
                    ins5(tops[mi * 2 + 1], c[mi][ni][3]);
                }
        }

        // fill next buffer
        if (st + 1 < NTILES) {
            unsigned* d = Ss + ((st + 1) & 1) * TILE_FLOATS + srow * STRIDE + shalf;
#pragma unroll
            for (int i = 0; i < 8; i++) {
                d[i * 4 + 0] = f2tf32(pf[i].x * pmag);
                d[i * 4 + 1] = f2tf32(pf[i].y * pmag);
                d[i * 4 + 2] = f2tf32(pf[i].z * pmag);
                d[i * 4 + 3] = f2tf32(pf[i].w * pmag);
            }
        }
        __syncthreads();
    }

    // --- top-5 cross-thread reduction via smem ---
    // candidates per row: 4 quad-lanes x 2 n-warps = 8, 5 values each.
    {
        const int slot_t = wn * 4 + kq;   // 0..7
#pragma unroll
        for (int s = 0; s < 4; s++) {
            const int row = wm * 32 + qd + s * 8;
            float* dst = red + (row * 8 + slot_t) * 5;
#pragma unroll
            for (int i = 0; i < 5; i++) dst[i] = tops[s][i];
        }
    }
    __syncthreads();

    if (tid < TM) {
        const float* src = red + tid * 40;
        float t[5];
#pragma unroll
        for (int i = 0; i < 5; i++) t[i] = -CUDART_INF_F;
#pragma unroll
        for (int j = 0; j < 40; j++) ins5(t, src[j]);
        float* orow = out + (size_t)(b * QQ + q0 + tid) * OUTC;
#pragma unroll
        for (int i = 0; i < 5; i++) orow[i] = t[i];
    }
}

// ---------------------------------------------------------------------------
extern "C" void kernel_launch(void* const* d_in, const int* in_sizes, int n_in,
                              void* d_out, int out_size) {
    const float* supp  = (const float*)d_in[0];
    const float* query = (const float*)d_in[1];
    float* out = (float*)d_out;

    const int smem_bytes = 3 * TILE_FLOATS * sizeof(unsigned);  // 104448
    cudaFuncSetAttribute(fused_kernel,
                         cudaFuncAttributeMaxDynamicSharedMemorySize, smem_bytes);

    mag_kernel<<<(BB * SS + 255) / 256, 256>>>(supp);

    dim3 grid(QQ / TM, BB);
    fused_kernel<<<grid, 256, smem_bytes>>>(supp, query, out);
}

// round 4
// speedup vs baseline: 2.0833x; 1.2444x over previous
#include <cuda_runtime.h>
#include <math_constants.h>
#include <cstdint>

// Problem constants (DistanceNetwork_17514876634042)
#define BB     8
#define SS     4096
#define QQ     4096
#define DD     64
#define BSHOT  2048
#define NTOP   5
#define OUTC   (NTOP + (SS - BSHOT))   // 2053

#define TM       128                 // q rows per CTA
#define TN       64                  // s cols per chunk
#define NCHUNK   (SS / TN)           // 64
#define TOPCHUNK (BSHOT / TN)        // 32

// Packed smem sizes (uint4 units)
#define APACK_U4 (8 * 8 * 32)        // [mt][ks][lane] -> 2048 uint4 = 32 KB
#define BPACK_U4 (4 * 8 * 32)        // [g2][ks][lane] -> 1024 uint4 = 16 KB per buffer

__device__ float g_mag[BB * SS];

// ---------------------------------------------------------------------------
__global__ void mag_kernel(const float* __restrict__ supp) {
    int i = blockIdx.x * blockDim.x + threadIdx.x;
    if (i >= BB * SS) return;
    const float* p = supp + (size_t)i * DD;
    float s = 0.f;
#pragma unroll
    for (int k = 0; k < DD; k += 4) {
        float4 v = *(const float4*)(p + k);
        s += v.x * v.x + v.y * v.y + v.z * v.z + v.w * v.w;
    }
    g_mag[i] = rsqrtf(fmaxf(s, 1e-10f));
}

// ---------------------------------------------------------------------------
__device__ __forceinline__ unsigned f2tf32(float f) {
    unsigned u; asm("cvt.rna.tf32.f32 %0, %1;" : "=r"(u) : "f"(f)); return u;
}

__device__ __forceinline__ void mma_tf32(float* c,
                                         const uint4& a, unsigned b0, unsigned b1) {
    asm volatile(
        "mma.sync.aligned.m16n8k8.row.col.f32.tf32.tf32.f32 "
        "{%0,%1,%2,%3}, {%4,%5,%6,%7}, {%8,%9}, {%0,%1,%2,%3};"
        : "+f"(c[0]), "+f"(c[1]), "+f"(c[2]), "+f"(c[3])
        : "r"(a.x), "r"(a.y), "r"(a.z), "r"(a.w), "r"(b0), "r"(b1));
}

__device__ __forceinline__ void ins5(float* t, float v) {
    if (v > t[4]) {
        t[4] = v;
        if (t[4] > t[3]) { float x = t[3]; t[3] = t[4]; t[4] = x;
            if (t[3] > t[2]) { x = t[2]; t[2] = t[3]; t[3] = x;
                if (t[2] > t[1]) { x = t[1]; t[1] = t[2]; t[2] = x;
                    if (t[1] > t[0]) { x = t[0]; t[0] = t[1]; t[1] = x; } } } }
    }
}

// ---------------------------------------------------------------------------
// Fused tf32-MMA cosine GEMM + direct tail store + register top-5.
// Grid (QQ/TM, BB) = 256 CTAs, 256 threads, 2 CTAs/SM -> exactly one wave.
// Warp wid: wm=wid&3 -> rows wm*32..+31; wn=wid>>2 -> cols wn*32..+31 of chunk.
// ---------------------------------------------------------------------------
extern __shared__ uint4 smem4[];

__global__ __launch_bounds__(256, 2)
void fused_kernel(const float* __restrict__ supp,
                  const float* __restrict__ query,
                  float* __restrict__ out) {
    uint4* Apack = smem4;                  // APACK_U4
    uint4* Bpack = smem4 + APACK_U4;       // 2 * BPACK_U4 (double buffer)
    float* red   = (float*)smem4;          // aliases Apack after the GEMM loop

    const int b    = blockIdx.y;
    const int q0   = blockIdx.x * TM;
    const int tid  = threadIdx.x;
    const int wid  = tid >> 5;
    const int lane = tid & 31;
    const int wm   = wid & 3;
    const int wn   = wid >> 2;
    const int qd   = lane >> 2;    // 0..7
    const int kq   = lane & 3;     // 0..3

    const float* qb = query + (size_t)b * QQ * DD;
    const float* sb = supp  + (size_t)b * SS * DD;

    // ---- fill A (query tile) into fragment-packed layout, tf32-rounded ----
    // thread = (ks = tid>>5, lane); iterates mt. Fragment a0..a3 order matches
    // mma.m16n8k8 A operand: (r,k),(r+8,k),(r,k+4),(r+8,k+4).
    {
        const int ks = tid >> 5;
        const int k  = ks * 8 + kq;
        const float* qrow = qb + (size_t)q0 * DD;
#pragma unroll
        for (int mt = 0; mt < 8; mt++) {
            const int r = mt * 16 + qd;
            uint4 u;
            u.x = f2tf32(qrow[(size_t)r * DD + k]);
            u.y = f2tf32(qrow[(size_t)(r + 8) * DD + k]);
            u.z = f2tf32(qrow[(size_t)r * DD + k + 4]);
            u.w = f2tf32(qrow[(size_t)(r + 8) * DD + k + 4]);
            Apack[(mt * 8 + ks) * 32 + lane] = u;
        }
    }

    // ---- B fill machinery ----
    // thread: srow = tid>>2 (0..63), kb = (tid&3)*16. Owns 16 consecutive k.
    const int srow = tid >> 2;
    const int kb   = (tid & 3) * 16;
    const int g2   = srow >> 4;          // 0..3
    const int half = (srow >> 3) & 1;    // which half of the uint4 pair
    const int lq   = srow & 7;

    float4 pf[4];
    float  pmag;

    // prefetch chunk 0
    {
        const float* p = sb + (size_t)srow * DD + kb;
#pragma unroll
        for (int j = 0; j < 4; j++) pf[j] = *(const float4*)(p + 4 * j);
        pmag = g_mag[b * SS + srow];
    }
    // store chunk 0 into buffer 0 (mag folded, tf32-rounded)
    {
        float v[16];
#pragma unroll
        for (int j = 0; j < 4; j++) {
            v[4 * j] = pf[j].x * pmag; v[4 * j + 1] = pf[j].y * pmag;
            v[4 * j + 2] = pf[j].z * pmag; v[4 * j + 3] = pf[j].w * pmag;
        }
        uint2* Bp2 = (uint2*)Bpack;
#pragma unroll
        for (int ks2 = 0; ks2 < 2; ks2++) {
            const int ks = (kb >> 3) + ks2;
#pragma unroll
            for (int q = 0; q < 4; q++) {
                uint2 val = make_uint2(f2tf32(v[ks2 * 8 + q]), f2tf32(v[ks2 * 8 + q + 4]));
                Bp2[((g2 * 8 + ks) * 32 + lq * 4 + q) * 2 + half] = val;
            }
        }
    }

    float tops[4][5];
#pragma unroll
    for (int s = 0; s < 4; s++)
#pragma unroll
        for (int i = 0; i < 5; i++) tops[s][i] = -CUDART_INF_F;

    for (int ch = 0; ch < NCHUNK; ++ch) {
        __syncthreads();   // B buf (ch&1) stores visible; buf ((ch+1)&1) free

        // prefetch next chunk (overlaps MMA via scoreboard)
        if (ch + 1 < NCHUNK) {
            const float* p = sb + (size_t)((ch + 1) * TN + srow) * DD + kb;
#pragma unroll
            for (int j = 0; j < 4; j++) pf[j] = *(const float4*)(p + 4 * j);
            pmag = g_mag[b * SS + (ch + 1) * TN + srow];
        }

        // ---- MMA over K=64 ----
        const uint4* Bp = Bpack + (ch & 1) * BPACK_U4;
        float c[2][4][4];
#pragma unroll
        for (int mi = 0; mi < 2; mi++)
#pragma unroll
            for (int ni = 0; ni < 4; ni++)
#pragma unroll
                for (int j = 0; j < 4; j++) c[mi][ni][j] = 0.f;

#pragma unroll
        for (int ks = 0; ks < 8; ks++) {
            const uint4 a0 = Apack[((wm * 2 + 0) * 8 + ks) * 32 + lane];
            const uint4 a1 = Apack[((wm * 2 + 1) * 8 + ks) * 32 + lane];
            const uint4 b0 = Bp[((wn * 2 + 0) * 8 + ks) * 32 + lane];
            const uint4 b1 = Bp[((wn * 2 + 1) * 8 + ks) * 32 + lane];
            mma_tf32(c[0][0], a0, b0.x, b0.y);
            mma_tf32(c[0][1], a0, b0.z, b0.w);
            mma_tf32(c[0][2], a0, b1.x, b1.y);
            mma_tf32(c[0][3], a0, b1.z, b1.w);
            mma_tf32(c[1][0], a1, b0.x, b0.y);
            mma_tf32(c[1][1], a1, b0.z, b0.w);
            mma_tf32(c[1][2], a1, b1.x, b1.y);
            mma_tf32(c[1][3], a1, b1.z, b1.w);
        }

        // ---- epilogue ----
        if (ch < TOPCHUNK) {
#pragma unroll
            for (int mi = 0; mi < 2; mi++)
#pragma unroll
                for (int ni = 0; ni < 4; ni++) {
                    ins5(tops[mi * 2 + 0], c[mi][ni][0]);
                    ins5(tops[mi * 2 + 0], c[mi][ni][1]);
                    ins5(tops[mi * 2 + 1], c[mi][ni][2]);
                    ins5(tops[mi * 2 + 1], c[mi][ni][3]);
                }
        } else {
            const size_t orow0 = (size_t)(b * QQ + q0);
            const int colbase = NTOP + (ch - TOPCHUNK) * TN + wn * 32;
#pragma unroll
            for (int mi = 0; mi < 2; mi++) {
                const int r = wm * 32 + mi * 16 + qd;
                float* p0 = out + (orow0 + r) * OUTC + colbase;
                float* p1 = out + (orow0 + r + 8) * OUTC + colbase;
#pragma unroll
                for (int ni = 0; ni < 4; ni++) {
                    const int cc = ni * 8 + 2 * kq;
                    p0[cc] = c[mi][ni][0]; p0[cc + 1] = c[mi][ni][1];
                    p1[cc] = c[mi][ni][2]; p1[cc + 1] = c[mi][ni][3];
                }
            }
        }

        // ---- store prefetched chunk into the other buffer ----
        if (ch + 1 < NCHUNK) {
            float v[16];
#pragma unroll
            for (int j = 0; j < 4; j++) {
                v[4 * j] = pf[j].x * pmag; v[4 * j + 1] = pf[j].y * pmag;
                v[4 * j + 2] = pf[j].z * pmag; v[4 * j + 3] = pf[j].w * pmag;
            }
            uint2* Bp2 = (uint2*)(Bpack + ((ch + 1) & 1) * BPACK_U4);
#pragma unroll
            for (int ks2 = 0; ks2 < 2; ks2++) {
                const int ks = (kb >> 3) + ks2;
#pragma unroll
                for (int q = 0; q < 4; q++) {
                    uint2 val = make_uint2(f2tf32(v[ks2 * 8 + q]), f2tf32(v[ks2 * 8 + q + 4]));
                    Bp2[((g2 * 8 + ks) * 32 + lq * 4 + q) * 2 + half] = val;
                }
            }
        }
    }

    // ---- top-5 cross-thread merge (red aliases Apack; safe after last MMA) ----
    __syncthreads();
    {
#pragma unroll
        for (int s = 0; s < 4; s++) {
            const int mi = s >> 1, h = s & 1;
            const int row = wm * 32 + mi * 16 + h * 8 + qd;
            float* dst = red + (row * 8 + wn * 4 + kq) * 5;
#pragma unroll
            for (int i = 0; i < 5; i++) dst[i] = tops[s][i];
        }
    }
    __syncthreads();
    if (tid < TM) {
        float t5[5];
#pragma unroll
        for (int i = 0; i < 5; i++) t5[i] = -CUDART_INF_F;
        const float* s = red + tid * 40;
#pragma unroll
        for (int j = 0; j < 40; j++) ins5(t5, s[j]);
        float* orow = out + (size_t)(b * QQ + q0 + tid) * OUTC;
#pragma unroll
        for (int i = 0; i < 5; i++) orow[i] = t5[i];
    }
}

// ---------------------------------------------------------------------------
extern "C" void kernel_launch(void* const* d_in, const int* in_sizes, int n_in,
                              void* d_out, int out_size) {
    const float* supp  = (const float*)d_in[0];
    const float* query = (const float*)d_in[1];
    float* out = (float*)d_out;

    const int smem_bytes = (APACK_U4 + 2 * BPACK_U4) * 16;   // 65536
    cudaFuncSetAttribute(fused_kernel,
                         cudaFuncAttributeMaxDynamicSharedMemorySize, smem_bytes);

    mag_kernel<<<(BB * SS + 255) / 256, 256>>>(supp);

    dim3 grid(QQ / TM, BB);
    fused_kernel<<<grid, 256, smem_bytes>>>(supp, query, out);
}

// round 5
// speedup vs baseline: 2.4029x; 1.1534x over previous
#include <cuda_runtime.h>
#include <cuda_fp16.h>
#include <math_constants.h>
#include <cstdint>

// Problem constants (DistanceNetwork_17514876634042)
#define BB     8
#define SS     4096
#define QQ     4096
#define DD     64
#define BSHOT  2048
#define NTOP   5
#define OUTC   (NTOP + (SS - BSHOT))   // 2053

#define TM       128                 // q rows per CTA
#define TN       64                  // s cols per chunk
#define NCHUNK   (SS / TN)           // 64
#define TOPCHUNK (BSHOT / TN)        // 32

// Packed smem sizes (uint4 units), fp16 fragments
#define APACK_U4 (8 * 4 * 32)        // [mt(8)][ks(4)][lane] = 1024 uint4 = 16 KB
#define BPACK_U4 (4 * 4 * 32)        // [g(4)][ks(4)][lane]  =  512 uint4 =  8 KB / buffer

__device__ float g_mag[BB * SS];

// ---------------------------------------------------------------------------
__global__ void mag_kernel(const float* __restrict__ supp) {
    int i = blockIdx.x * blockDim.x + threadIdx.x;
    if (i >= BB * SS) return;
    const float* p = supp + (size_t)i * DD;
    float s = 0.f;
#pragma unroll
    for (int k = 0; k < DD; k += 4) {
        float4 v = *(const float4*)(p + k);
        s += v.x * v.x + v.y * v.y + v.z * v.z + v.w * v.w;
    }
    g_mag[i] = rsqrtf(fmaxf(s, 1e-10f));
}

// ---------------------------------------------------------------------------
__device__ __forceinline__ unsigned h2(float lo, float hi) {
    __half2 h = __floats2half2_rn(lo, hi);
    return *(unsigned*)&h;
}

__device__ __forceinline__ void mma_f16(float* c, const uint4& a,
                                        unsigned b0, unsigned b1) {
    asm volatile(
        "mma.sync.aligned.m16n8k16.row.col.f32.f16.f16.f32 "
        "{%0,%1,%2,%3}, {%4,%5,%6,%7}, {%8,%9}, {%0,%1,%2,%3};"
        : "+f"(c[0]), "+f"(c[1]), "+f"(c[2]), "+f"(c[3])
        : "r"(a.x), "r"(a.y), "r"(a.z), "r"(a.w), "r"(b0), "r"(b1));
}

__device__ __forceinline__ void ins5(float* t, float v) {
    if (v > t[4]) {
        t[4] = v;
        if (t[4] > t[3]) { float x = t[3]; t[3] = t[4]; t[4] = x;
            if (t[3] > t[2]) { x = t[2]; t[2] = t[3]; t[3] = x;
                if (t[2] > t[1]) { x = t[1]; t[1] = t[2]; t[2] = x;
                    if (t[1] > t[0]) { x = t[0]; t[0] = t[1]; t[1] = x; } } } }
    }
}

// ---------------------------------------------------------------------------
// Fused fp16-MMA cosine GEMM + direct tail store + register top-5.
// Grid (QQ/TM, BB) = 256 CTAs, 256 threads, 2 CTAs/SM -> one wave.
// Warp wid: wm=wid&3 -> rows wm*32..+31; wn=wid>>2 -> cols wn*32..+31 of chunk.
// ---------------------------------------------------------------------------
extern __shared__ uint4 smem4[];

__global__ __launch_bounds__(256, 2)
void fused_kernel(const float* __restrict__ supp,
                  const float* __restrict__ query,
                  float* __restrict__ out) {
    uint4* Apack = smem4;                  // APACK_U4
    uint4* Bpack = smem4 + APACK_U4;       // 2 * BPACK_U4 (double buffer)
    float* red   = (float*)smem4;          // aliases all tiles after GEMM loop

    const int b    = blockIdx.y;
    const int q0   = blockIdx.x * TM;
    const int tid  = threadIdx.x;
    const int wid  = tid >> 5;
    const int lane = tid & 31;
    const int wm   = wid & 3;
    const int wn   = wid >> 2;
    const int qd   = lane >> 2;    // 0..7
    const int kq   = lane & 3;     // 0..3

    const float* qb = query + (size_t)b * QQ * DD;
    const float* sb = supp  + (size_t)b * SS * DD;

    // ---- fill A (query tile) into m16n8k16 fragment layout, fp16 ----
    // 32 jobs = ks(4) x mt(8); warp w takes jobs w*4..w*4+3.
    {
#pragma unroll
        for (int i = 0; i < 4; i++) {
            const int j  = wid * 4 + i;
            const int ks = j >> 3;
            const int mt = j & 7;
            const int r  = mt * 16 + qd;
            const int k  = ks * 16 + 2 * kq;
            const float* base = qb + (size_t)(q0 + r) * DD + k;
            float2 v00 = *(const float2*)(base);
            float2 v10 = *(const float2*)(base + 8 * DD);
            float2 v01 = *(const float2*)(base + 8);
            float2 v11 = *(const float2*)(base + 8 * DD + 8);
            uint4 u;
            u.x = h2(v00.x, v00.y);   // a0: (r,   k), (r,   k+1)
            u.y = h2(v10.x, v10.y);   // a1: (r+8, k), (r+8, k+1)
            u.z = h2(v01.x, v01.y);   // a2: (r,   k+8), (r, k+9)
            u.w = h2(v11.x, v11.y);   // a3: (r+8, k+8), ...
            Apack[(mt * 4 + ks) * 32 + lane] = u;
        }
    }

    // ---- B fill machinery ----
    // thread: brow = tid>>2 (0..63), bks = tid&3 -> owns 16 consecutive k of one row.
    const int brow = tid >> 2;
    const int bks  = tid & 3;
    const int bnt  = brow >> 3;          // n8 tile 0..7
    const int bg   = bnt >> 1;           // uint4 group 0..3
    const int bsub = bnt & 1;
    const int blb  = (brow & 7) * 4;     // target lane base

    float4 pf[4];
    float  pmag;

    // prefetch chunk 0
    {
        const float* p = sb + (size_t)brow * DD + bks * 16;
#pragma unroll
        for (int j = 0; j < 4; j++) pf[j] = *(const float4*)(p + 4 * j);
        pmag = g_mag[b * SS + brow];
    }
    // store chunk 0 into buffer 0 (mag folded -> unit-norm cols, fp16-safe)
    {
        float v[16];
#pragma unroll
        for (int j = 0; j < 4; j++) {
            v[4 * j] = pf[j].x * pmag; v[4 * j + 1] = pf[j].y * pmag;
            v[4 * j + 2] = pf[j].z * pmag; v[4 * j + 3] = pf[j].w * pmag;
        }
        uint2* Bp2 = (uint2*)Bpack;
#pragma unroll
        for (int q = 0; q < 4; q++) {
            unsigned b0 = h2(v[2 * q], v[2 * q + 1]);
            unsigned b1 = h2(v[8 + 2 * q], v[9 + 2 * q]);
            Bp2[((bg * 4 + bks) * 32 + blb + q) * 2 + bsub] = make_uint2(b0, b1);
        }
    }

    float tops[4][5];
#pragma unroll
    for (int s = 0; s < 4; s++)
#pragma unroll
        for (int i = 0; i < 5; i++) tops[s][i] = -CUDART_INF_F;

    for (int ch = 0; ch < NCHUNK; ++ch) {
        __syncthreads();   // buf (ch&1) ready; buf ((ch+1)&1) free

        // prefetch next chunk (overlaps MMA via scoreboard)
        if (ch + 1 < NCHUNK) {
            const float* p = sb + (size_t)((ch + 1) * TN + brow) * DD + bks * 16;
#pragma unroll
            for (int j = 0; j < 4; j++) pf[j] = *(const float4*)(p + 4 * j);
            pmag = g_mag[b * SS + (ch + 1) * TN + brow];
        }

        // ---- MMA over K=64 (4 k16-steps) ----
        const uint4* Bp = Bpack + (ch & 1) * BPACK_U4;
        float c[2][4][4];
#pragma unroll
        for (int mi = 0; mi < 2; mi++)
#pragma unroll
            for (int ni = 0; ni < 4; ni++)
#pragma unroll
                for (int j = 0; j < 4; j++) c[mi][ni][j] = 0.f;

#pragma unroll
        for (int ks = 0; ks < 4; ks++) {
            const uint4 a0 = Apack[((wm * 2 + 0) * 4 + ks) * 32 + lane];
            const uint4 a1 = Apack[((wm * 2 + 1) * 4 + ks) * 32 + lane];
            const uint4 B0 = Bp[((wn * 2 + 0) * 4 + ks) * 32 + lane];
            const uint4 B1 = Bp[((wn * 2 + 1) * 4 + ks) * 32 + lane];
            mma_f16(c[0][0], a0, B0.x, B0.y);
            mma_f16(c[0][1], a0, B0.z, B0.w);
            mma_f16(c[0][2], a0, B1.x, B1.y);
            mma_f16(c[0][3], a0, B1.z, B1.w);
            mma_f16(c[1][0], a1, B0.x, B0.y);
            mma_f16(c[1][1], a1, B0.z, B0.w);
            mma_f16(c[1][2], a1, B1.x, B1.y);
            mma_f16(c[1][3], a1, B1.z, B1.w);
        }

        // ---- epilogue ----
        if (ch < TOPCHUNK) {
#pragma unroll
            for (int mi = 0; mi < 2; mi++)
#pragma unroll
                for (int ni = 0; ni < 4; ni++) {
                    ins5(tops[mi * 2 + 0], c[mi][ni][0]);
                    ins5(tops[mi * 2 + 0], c[mi][ni][1]);
                    ins5(tops[mi * 2 + 1], c[mi][ni][2]);
                    ins5(tops[mi * 2 + 1], c[mi][ni][3]);
                }
        } else {
            const size_t orow0 = (size_t)(b * QQ + q0);
            const int colbase = NTOP + (ch - TOPCHUNK) * TN + wn * 32;
#pragma unroll
            for (int mi = 0; mi < 2; mi++) {
                const int r = wm * 32 + mi * 16 + qd;
                float* p0 = out + (orow0 + r) * OUTC + colbase;
                float* p1 = out + (orow0 + r + 8) * OUTC + colbase;
#pragma unroll
                for (int ni = 0; ni < 4; ni++) {
                    const int cc = ni * 8 + 2 * kq;
                    p0[cc] = c[mi][ni][0]; p0[cc + 1] = c[mi][ni][1];
                    p1[cc] = c[mi][ni][2]; p1[cc + 1] = c[mi][ni][3];
                }
            }
        }

        // ---- store prefetched chunk into the other buffer ----
        if (ch + 1 < NCHUNK) {
            float v[16];
#pragma unroll
            for (int j = 0; j < 4; j++) {
                v[4 * j] = pf[j].x * pmag; v[4 * j + 1] = pf[j].y * pmag;
                v[4 * j + 2] = pf[j].z * pmag; v[4 * j + 3] = pf[j].w * pmag;
            }
            uint2* Bp2 = (uint2*)(Bpack + ((ch + 1) & 1) * BPACK_U4);
#pragma unroll
            for (int q = 0; q < 4; q++) {
                unsigned b0 = h2(v[2 * q], v[2 * q + 1]);
                unsigned b1 = h2(v[8 + 2 * q], v[9 + 2 * q]);
                Bp2[((bg * 4 + bks) * 32 + blb + q) * 2 + bsub] = make_uint2(b0, b1);
            }
        }
    }

    // ---- top-5 cross-thread merge (red aliases tiles; all dead now) ----
    __syncthreads();
    {
#pragma unroll
        for (int s = 0; s < 4; s++) {
            const int mi = s >> 1, h = s & 1;
            const int row = wm * 32 + mi * 16 + h * 8 + qd;
            float* dst = red + (row * 8 + wn * 4 + kq) * 5;
#pragma unroll
            for (int i = 0; i < 5; i++) dst[i] = tops[s][i];
        }
    }
    __syncthreads();
    if (tid < TM) {
        float t5[5];
#pragma unroll
        for (int i = 0; i < 5; i++) t5[i] = -CUDART_INF_F;
        const float* s = red + tid * 40;
#pragma unroll
        for (int j = 0; j < 40; j++) ins5(t5, s[j]);
        float* orow = out + (size_t)(b * QQ + q0 + tid) * OUTC;
#pragma unroll
        for (int i = 0; i < 5; i++) orow[i] = t5[i];
    }
}

// ---------------------------------------------------------------------------
extern "C" void kernel_launch(void* const* d_in, const int* in_sizes, int n_in,
                              void* d_out, int out_size) {
    const float* supp  = (const float*)d_in[0];
    const float* query = (const float*)d_in[1];
    float* out = (float*)d_out;

    const int smem_bytes = (APACK_U4 + 2 * BPACK_U4) * 16;   // 32768
    cudaFuncSetAttribute(fused_kernel,
                         cudaFuncAttributeMaxDynamicSharedMemorySize, smem_bytes);

    mag_kernel<<<(BB * SS + 255) / 256, 256>>>(supp);

    dim3 grid(QQ / TM, BB);
    fused_kernel<<<grid, 256, smem_bytes>>>(supp, query, out);
}

// round 7
// speedup vs baseline: 2.4971x; 1.0392x over previous
#include <cuda_runtime.h>
#include <cuda_fp16.h>
#include <math_constants.h>
#include <cstdint>

// Problem constants (DistanceNetwork_17514876634042)
#define BB     8
#define SS     4096
#define QQ     4096
#define DD     64
#define BSHOT  2048
#define NTOP   5
#define OUTC   (NTOP + (SS - BSHOT))   // 2053

#define TM       128                 // q rows per CTA
#define TN       64                  // s cols per chunk
#define NCHUNK   (SS / TN)           // 64
#define TOPCHUNK (BSHOT / TN)        // 32
#define NSTAGE   4

#define APACK_U4 (8 * 4 * 32)        // A: [mt(8)][ks(4)][lane] = 1024 uint4 = 16 KB
#define BPACK_U4 (4 * 4 * 32)        // B: [g(4)][ks(4)][lane]  =  512 uint4 =  8 KB / stage

// Pre-packed fp16 support fragments (mag folded): [b][chunk][BPACK_U4]
__device__ uint4 g_pack[(size_t)BB * NCHUNK * BPACK_U4];   // 4 MB

// ---------------------------------------------------------------------------
__device__ __forceinline__ unsigned h2(float lo, float hi) {
    __half2 h = __floats2half2_rn(lo, hi);
    return *(unsigned*)&h;
}

// Pre-kernel: one thread per support row. Computes rsqrt-magnitude, folds it,
// converts to fp16 and scatters into the m16n8k16 B-fragment layout.
__global__ void pack_kernel(const float* __restrict__ supp) {
    const int i = blockIdx.x * blockDim.x + threadIdx.x;
    if (i >= BB * SS) return;
    const int b    = i / SS;
    const int s    = i % SS;
    const int ch   = s / TN;
    const int srow = s % TN;

    const float* p = supp + (size_t)i * DD;
    float v[DD];
    float sum = 0.f;
#pragma unroll
    for (int k = 0; k < DD; k += 4) {
        float4 x = *(const float4*)(p + k);
        v[k] = x.x; v[k + 1] = x.y; v[k + 2] = x.z; v[k + 3] = x.w;
        sum += x.x * x.x + x.y * x.y + x.z * x.z + x.w * x.w;
    }
    const float mag = rsqrtf(fmaxf(sum, 1e-10f));
#pragma unroll
    for (int k = 0; k < DD; k++) v[k] *= mag;

    const int bnt  = srow >> 3;        // n8 tile 0..7
    const int bg   = bnt >> 1;         // uint4 group 0..3
    const int bsub = bnt & 1;
    const int blb  = (srow & 7) * 4;   // lane base

    uint2* dst = (uint2*)(g_pack + ((size_t)b * NCHUNK + ch) * BPACK_U4);
#pragma unroll
    for (int ks = 0; ks < 4; ks++) {
        const int k0 = ks * 16;
#pragma unroll
        for (int q = 0; q < 4; q++) {
            unsigned b0 = h2(v[k0 + 2 * q],     v[k0 + 2 * q + 1]);
            unsigned b1 = h2(v[k0 + 8 + 2 * q], v[k0 + 9 + 2 * q]);
            dst[((bg * 4 + ks) * 32 + blb + q) * 2 + bsub] = make_uint2(b0, b1);
        }
    }
}

// ---------------------------------------------------------------------------
__device__ __forceinline__ void mma_f16(float* c, const uint4& a,
                                        unsigned b0, unsigned b1) {
    asm volatile(
        "mma.sync.aligned.m16n8k16.row.col.f32.f16.f16.f32 "
        "{%0,%1,%2,%3}, {%4,%5,%6,%7}, {%8,%9}, {%0,%1,%2,%3};"
        : "+f"(c[0]), "+f"(c[1]), "+f"(c[2]), "+f"(c[3])
        : "r"(a.x), "r"(a.y), "r"(a.z), "r"(a.w), "r"(b0), "r"(b1));
}

__device__ __forceinline__ unsigned smem_u32(const void* p) {
    unsigned a;
    asm("{ .reg .u64 t; cvta.to.shared.u64 t, %1; cvt.u32.u64 %0, t; }" : "=r"(a) : "l"(p));
    return a;
}
__device__ __forceinline__ void cp_async16(unsigned dst, const void* src) {
    asm volatile("cp.async.cg.shared.global [%0], [%1], 16;" :: "r"(dst), "l"(src));
}
#define CP_COMMIT() asm volatile("cp.async.commit_group;" ::: "memory")
#define CP_WAIT2()  asm volatile("cp.async.wait_group 2;" ::: "memory")

__device__ __forceinline__ void ins5(float* t, float v) {
    if (v > t[4]) {
        t[4] = v;
        if (t[4] > t[3]) { float x = t[3]; t[3] = t[4]; t[4] = x;
            if (t[3] > t[2]) { x = t[2]; t[2] = t[3]; t[3] = x;
                if (t[2] > t[1]) { x = t[1]; t[1] = t[2]; t[2] = x;
                    if (t[1] > t[0]) { x = t[0]; t[0] = t[1]; t[1] = x; } } } }
    }
}

// ---------------------------------------------------------------------------
// Fused fp16-MMA cosine GEMM + direct tail store + register top-5.
// Grid (QQ/TM, BB) = 256 CTAs, 256 threads, 2 CTAs/SM.
// A fragments live in registers; B streams through a 4-stage cp.async ring.
// ---------------------------------------------------------------------------
extern __shared__ uint4 smem4[];

__global__ __launch_bounds__(256, 2)
void fused_kernel(const float* __restrict__ query,
                  float* __restrict__ out) {
    uint4* Apack  = smem4;                        // APACK_U4 (dead after hoist)
    uint4* Bstage = smem4 + APACK_U4;             // NSTAGE * BPACK_U4
    float* red    = (float*)smem4;                // aliases everything at the end

    const int b    = blockIdx.y;
    const int q0   = blockIdx.x * TM;
    const int tid  = threadIdx.x;
    const int wid  = tid >> 5;
    const int lane = tid & 31;
    const int wm   = wid & 3;
    const int wn   = wid >> 2;
    const int qd   = lane >> 2;    // 0..7
    const int kq   = lane & 3;     // 0..3

    const float* qb = query + (size_t)b * QQ * DD;

    // ---- fill A (query tile) into fragment layout, fp16 ----
    {
#pragma unroll
        for (int i = 0; i < 4; i++) {
            const int j  = wid * 4 + i;
            const int ks = j >> 3;
            const int mt = j & 7;
            const int r  = mt * 16 + qd;
            const int k  = ks * 16 + 2 * kq;
            const float* base = qb + (size_t)(q0 + r) * DD + k;
            float2 v00 = *(const float2*)(base);
            float2 v10 = *(const float2*)(base + 8 * DD);
            float2 v01 = *(const float2*)(base + 8);
            float2 v11 = *(const float2*)(base + 8 * DD + 8);
            uint4 u;
            u.x = h2(v00.x, v00.y);
            u.y = h2(v10.x, v10.y);
            u.z = h2(v01.x, v01.y);
            u.w = h2(v11.x, v11.y);
            Apack[(mt * 4 + ks) * 32 + lane] = u;
        }
    }

    // ---- prologue: issue cp.async for chunks 0..2 ----
    const uint4* gsrc = g_pack + (size_t)b * NCHUNK * BPACK_U4;
    const unsigned bst_base = smem_u32(Bstage);
#pragma unroll
    for (int pchunk = 0; pchunk < NSTAGE - 1; pchunk++) {
        const unsigned dst = bst_base + (unsigned)((pchunk & (NSTAGE - 1)) * BPACK_U4 + 2 * tid) * 16u;
        const uint4* src = gsrc + (size_t)pchunk * BPACK_U4 + 2 * tid;
        cp_async16(dst, src);
        cp_async16(dst + 16, src + 1);
        CP_COMMIT();
    }

    __syncthreads();

    // ---- hoist A fragments into registers (invariant over all chunks) ----
    uint4 afrag[2][4];
#pragma unroll
    for (int mi = 0; mi < 2; mi++)
#pragma unroll
        for (int ks = 0; ks < 4; ks++)
            afrag[mi][ks] = Apack[((wm * 2 + mi) * 4 + ks) * 32 + lane];

    float tops[4][5];
#pragma unroll
    for (int s = 0; s < 4; s++)
#pragma unroll
        for (int i = 0; i < 5; i++) tops[s][i] = -CUDART_INF_F;

    for (int ch = 0; ch < NCHUNK; ++ch) {
        CP_WAIT2();          // group for chunk ch complete
        __syncthreads();     // all warps done reading stage (ch-1)&3

        // issue copy for chunk ch+3 into stage (ch+3)&3 (just freed)
        if (ch + NSTAGE - 1 < NCHUNK) {
            const int nc = ch + NSTAGE - 1;
            const unsigned dst = bst_base + (unsigned)((nc & (NSTAGE - 1)) * BPACK_U4 + 2 * tid) * 16u;
            const uint4* src = gsrc + (size_t)nc * BPACK_U4 + 2 * tid;
            cp_async16(dst, src);
            cp_async16(dst + 16, src + 1);
        }
        CP_COMMIT();         // always commit (empty groups keep wait arithmetic uniform)

        // ---- MMA over K=64 (4 k16-steps) ----
        const uint4* Bp = Bstage + (ch & (NSTAGE - 1)) * BPACK_U4;
        float c[2][4][4];
#pragma unroll
        for (int mi = 0; mi < 2; mi++)
#pragma unroll
            for (int ni = 0; ni < 4; ni++)
#pragma unroll
                for (int j = 0; j < 4; j++) c[mi][ni][j] = 0.f;

#pragma unroll
        for (int ks = 0; ks < 4; ks++) {
            const uint4 B0 = Bp[((wn * 2 + 0) * 4 + ks) * 32 + lane];
            const uint4 B1 = Bp[((wn * 2 + 1) * 4 + ks) * 32 + lane];
            mma_f16(c[0][0], afrag[0][ks], B0.x, B0.y);
            mma_f16(c[0][1], afrag[0][ks], B0.z, B0.w);
            mma_f16(c[0][2], afrag[0][ks], B1.x, B1.y);
            mma_f16(c[0][3], afrag[0][ks], B1.z, B1.w);
            mma_f16(c[1][0], afrag[1][ks], B0.x, B0.y);
            mma_f16(c[1][1], afrag[1][ks], B0.z, B0.w);
            mma_f16(c[1][2], afrag[1][ks], B1.x, B1.y);
            mma_f16(c[1][3], afrag[1][ks], B1.z, B1.w);
        }

        // ---- epilogue ----
        if (ch < TOPCHUNK) {
#pragma unroll
            for (int mi = 0; mi < 2; mi++)
#pragma unroll
                for (int ni = 0; ni < 4; ni++) {
                    ins5(tops[mi * 2 + 0], c[mi][ni][0]);
                    ins5(tops[mi * 2 + 0], c[mi][ni][1]);
                    ins5(tops[mi * 2 + 1], c[mi][ni][2]);
                    ins5(tops[mi * 2 + 1], c[mi][ni][3]);
                }
        } else {
            const size_t orow0 = (size_t)(b * QQ + q0);
            const int colbase = NTOP + (ch - TOPCHUNK) * TN + wn * 32;
#pragma unroll
            for (int mi = 0; mi < 2; mi++) {
                const int r = wm * 32 + mi * 16 + qd;
                float* p0 = out + (orow0 + r) * OUTC + colbase;
                float* p1 = out + (orow0 + r + 8) * OUTC + colbase;
#pragma unroll
                for (int ni = 0; ni < 4; ni++) {
                    const int cc = ni * 8 + 2 * kq;
                    p0[cc]     = c[mi][ni][0];   // scalar stores: OUTC is odd,
                    p0[cc + 1] = c[mi][ni][1];   // float2 would misalign
                    p1[cc]     = c[mi][ni][2];
                    p1[cc + 1] = c[mi][ni][3];
                }
            }
        }
    }

    // ---- top-5 cross-thread merge (red aliases dead smem) ----
    __syncthreads();
    {
#pragma unroll
        for (int s = 0; s < 4; s++) {
            const int mi = s >> 1, h = s & 1;
            const int row = wm * 32 + mi * 16 + h * 8 + qd;
            float* dst = red + (row * 8 + wn * 4 + kq) * 5;
#pragma unroll
            for (int i = 0; i < 5; i++) dst[i] = tops[s][i];
        }
    }
    __syncthreads();
    if (tid < TM) {
        float t5[5];
#pragma unroll
        for (int i = 0; i < 5; i++) t5[i] = -CUDART_INF_F;
        const float* s = red + tid * 40;
#pragma unroll
        for (int j = 0; j < 40; j++) ins5(t5, s[j]);
        float* orow = out + (size_t)(b * QQ + q0 + tid) * OUTC;
#pragma unroll
        for (int i = 0; i < 5; i++) orow[i] = t5[i];
    }
}

// ---------------------------------------------------------------------------
extern "C" void kernel_launch(void* const* d_in, const int* in_sizes, int n_in,
                              void* d_out, int out_size) {
    const float* supp  = (const float*)d_in[0];
    const float* query = (const float*)d_in[1];
    float* out = (float*)d_out;

    const int smem_bytes = (APACK_U4 + NSTAGE * BPACK_U4) * 16;   // 49152
    cudaFuncSetAttribute(fused_kernel,
                         cudaFuncAttributeMaxDynamicSharedMemorySize, smem_bytes);

    pack_kernel<<<(BB * SS + 127) / 128, 128>>>(supp);

    dim3 grid(QQ / TM, BB);
    fused_kernel<<<grid, 256, smem_bytes>>>(query, out);
}